// round 15
// baseline (speedup 1.0000x reference)
#include <cuda_runtime.h>
#include <cuda_bf16.h>
#include <math.h>
#include <stdint.h>

// Shape fixed by dataset: x[4,4096,64], y[4,4096,64], mu[64,1], logs2diag[64]
// R15: occupancy push. R14 profile: occ 23% (16 warps/SM), tensor 51%, L1 71%
// -> latency-exposure-bound, no pipe saturated. This round: 128x64 CTA tile,
// warp tile 32x32 (acc 32 regs), ~80 regs -> __launch_bounds__(256,3),
// smem 51KB -> 3 CTAs/SM = 24 warps. LDSM front-loaded per ks for MLP.
#define BB 4
#define NN 4096
#define MM 4096
#define DD 64

// ---------------- device scratch (no allocation allowed) -------------------
// Row layout: 16 uint4 = [hi: 8 uint4 (K=64 bf16)][lo: 8 uint4]
__device__ uint4  g_XE[BB * NN * 16];
__device__ uint4  g_YE[BB * MM * 16];
__device__ float4 g_xr[BB * NN];   // {cos(mx), sin(mx), 0.5*||x_||^2*log2e, 0}
__device__ float4 g_yr[BB * MM];

__device__ __forceinline__ uint32_t smem_u32(const void* p) {
    uint32_t a;
    asm("{ .reg .u64 t; cvta.to.shared.u64 t, %1; cvt.u32.u64 %0, t; }" : "=r"(a) : "l"(p));
    return a;
}

#define SWZ(o) ((o) ^ (((o) >> 3) & 0x70))

#define CP_ASYNC16(dst, src) \
    asm volatile("cp.async.cg.shared.global [%0], [%1], 16;" \
                 :: "r"(dst), "l"(src) : "memory")
#define CP_COMMIT() asm volatile("cp.async.commit_group;" ::: "memory")
#define CP_WAIT(n)  asm volatile("cp.async.wait_group %0;" :: "n"(n) : "memory")

#define LDSM_X4(r0, r1, r2, r3, addr)                                        \
    asm volatile("ldmatrix.sync.aligned.m8n8.x4.shared.b16 {%0,%1,%2,%3}, [%4];" \
                 : "=r"(r0), "=r"(r1), "=r"(r2), "=r"(r3) : "r"(addr))

#define MMA16816(d, a0, a1, a2, a3, b0, b1)                                  \
    asm volatile("mma.sync.aligned.m16n8k16.row.col.f32.bf16.bf16.f32 "      \
        "{%0,%1,%2,%3}, {%4,%5,%6,%7}, {%8,%9}, {%0,%1,%2,%3};"              \
        : "+f"((d)[0]), "+f"((d)[1]), "+f"((d)[2]), "+f"((d)[3])             \
        : "r"(a0), "r"(a1), "r"(a2), "r"(a3), "r"(b0), "r"(b1))

// ---------------- SMEM layout (~51KB -> 3 CTAs/SM) --------------------------
static constexpr int SEG_AH = 0;         // Ahi: 128 rows x 128B SW128 (16KB)
static constexpr int SEG_AL = 16384;     // Alo (16KB)
static constexpr int SEG_BH = 32768;     // Bhi: 64 rows x 128B (8KB)
static constexpr int SEG_BL = 40960;     // Blo (8KB)
static constexpr int OFF_XI = 49152;     // float4[128] (2KB)
static constexpr int OFF_YI = 51200;     // float4[64]  (1KB)
static constexpr int SMEM_TOTAL = 52224;

// ---------------------------------------------------------------------------
// Pass 1 (single launch, gridDim.y=2): per-row precompute + bf16 split.
//   Row layout out: [hi(8 uint4) | lo(8 uint4)]
// ---------------------------------------------------------------------------
__global__ void precomp_kernel(const float* __restrict__ x,
                               const float* __restrict__ y,
                               const float* __restrict__ mu,
                               const float* __restrict__ logs2)
{
    int gw  = (blockIdx.x * blockDim.x + threadIdx.x) >> 5;  // row within side
    int l   = threadIdx.x & 31;
    int isY = blockIdx.y;
    const float* src = isY ? y : x;

    float2 v   = ((const float2*)src)[gw * 32 + l];
    float2 muv = ((const float2*)mu)[l];
    float2 ls  = ((const float2*)logs2)[l];

    float s0 = expf(0.5f * ls.x), s1 = expf(0.5f * ls.y);
    float a = v.x * s0, c = v.y * s1;
    float m  = fmaf(v.x, muv.x, v.y * muv.y);
    float ss = fmaf(a, a, c * c);
#pragma unroll
    for (int o = 16; o > 0; o >>= 1) {
        m  += __shfl_xor_sync(0xffffffffu, m, o);
        ss += __shfl_xor_sync(0xffffffffu, ss, o);
    }

    __nv_bfloat16 h0 = __float2bfloat16(a);
    __nv_bfloat16 h1 = __float2bfloat16(c);
    __nv_bfloat16 l0 = __float2bfloat16(a - __bfloat162float(h0));
    __nv_bfloat16 l1 = __float2bfloat16(c - __bfloat162float(h1));
    uint32_t hi = ((uint32_t)__bfloat16_as_ushort(h1) << 16) | __bfloat16_as_ushort(h0);
    uint32_t lo = ((uint32_t)__bfloat16_as_ushort(l1) << 16) | __bfloat16_as_ushort(l0);

    uint32_t* dst = (uint32_t*)(isY ? g_YE : g_XE) + (size_t)gw * 64;
    dst[l] = hi; dst[32 + l] = lo;

    if (l == 0) {
        float sn, cs;
        sincosf(m, &sn, &cs);
        float4* ri = isY ? g_yr : g_xr;
        ri[gw] = make_float4(cs, sn, 0.5f * ss * 1.44269504f, 0.f);
    }
}

// ---------------------------------------------------------------------------
// Pass 2: dedup split-bf16 mma.sync GEMM + fused epilogue.
//   CTA: 128x64 tile, 256 threads = 8 warps (4x2), warp tile 32x32.
//   Per K16-step: all 8 LDSM.x4 front-loaded, then 24 MMAs
//   (hi.hi + lo.hi + hi.lo with hi fragments register-reused).
// ---------------------------------------------------------------------------
__global__ void __launch_bounds__(256, 3)
pairwise_kernel(float* __restrict__ out)
{
    extern __shared__ char smem[];
    const uint32_t base = smem_u32(smem);
    const int tid = threadIdx.x;
    const int wid = tid >> 5;
    const int l   = tid & 31;
    const int wy  = wid >> 1;           // 0..3 : row block (32 rows)
    const int wx  = wid & 1;            // 0..1 : col block (32 cols)

    const int b  = blockIdx.z;
    const int n0 = blockIdx.y * 128;
    const int m0 = blockIdx.x * 64;

    const uint4* Ag = g_XE + ((size_t)b * NN + n0) * 16;
    const uint4* Bg = g_YE + ((size_t)b * MM + m0) * 16;

    // ---- cp.async: 2 groups split by K-half (logical c16 0..3 then 4..7) ----
#pragma unroll
    for (int half = 0; half < 2; half++) {
        // A: 128 rows x 4 c16 = 512 uint4 per seg-half -> 2 per thread per seg
#pragma unroll
        for (int i = 0; i < 2; i++) {
            int f   = i * 256 + tid;
            int row = f >> 2;
            int c16 = (f & 3) + half * 4;
            uint32_t soff = SWZ((uint32_t)(row * 128 + c16 * 16));
            CP_ASYNC16(base + SEG_AH + soff, (const void*)(Ag + row * 16 + c16));
            CP_ASYNC16(base + SEG_AL + soff, (const void*)(Ag + row * 16 + 8 + c16));
        }
        // B: 64 rows x 4 c16 = 256 uint4 per seg-half -> 1 per thread per seg
        {
            int row = tid >> 2;
            int c16 = (tid & 3) + half * 4;
            uint32_t soff = SWZ((uint32_t)(row * 128 + c16 * 16));
            CP_ASYNC16(base + SEG_BH + soff, (const void*)(Bg + row * 16 + c16));
            CP_ASYNC16(base + SEG_BL + soff, (const void*)(Bg + row * 16 + 8 + c16));
        }
        CP_COMMIT();
    }

    // ---- row-info staging (covered by first syncthreads) ----
    if (tid < 128)
        *(float4*)(smem + OFF_XI + tid * 16) = g_xr[(size_t)b * NN + n0 + tid];
    else if (tid < 192)
        *(float4*)(smem + OFF_YI + (tid - 128) * 16) = g_yr[(size_t)b * MM + m0 + (tid - 128)];

    // ---- per-lane ldmatrix address components ----
    const int arow  = wy * 32 + (l & 15);
    const uint32_t axor  = (uint32_t)((l & 7) * 16);
    const uint32_t ahalf = (uint32_t)((l >> 4) * 16);
    const int g     = l >> 3;
    const int brow  = wx * 32 + (g & 2) * 4 + (l & 7);
    const uint32_t bxor  = (uint32_t)((l & 7) * 16);
    const uint32_t bhalf = (uint32_t)((g & 1) * 16);

    float acc[2][4][4];
#pragma unroll
    for (int mt = 0; mt < 2; mt++)
#pragma unroll
        for (int nt = 0; nt < 4; nt++)
#pragma unroll
            for (int e = 0; e < 4; e++) acc[mt][nt][e] = 0.f;

    // ---- mainloop: 4 K16-steps, fragments front-loaded, 3 products reuse hi ----
#pragma unroll
    for (int ks = 0; ks < 4; ks++) {
        if (ks == 0)      { CP_WAIT(1); __syncthreads(); }
        else if (ks == 2) { CP_WAIT(0); __syncthreads(); }

        const uint32_t kb   = (uint32_t)(ks * 32);
        const uint32_t aoff = (uint32_t)(arow * 128) + ((kb + ahalf) ^ axor);
        const uint32_t boff = (uint32_t)(brow * 128) + ((kb + bhalf) ^ bxor);

        // front-load all fragments (8 independent LDSM.x4)
        uint32_t bh[4][2], bl[4][2];
#pragma unroll
        for (int p = 0; p < 2; p++) {
            uint32_t r0, r1, r2, r3;
            LDSM_X4(r0, r1, r2, r3, base + SEG_BH + boff + (uint32_t)(p * 2048));
            bh[p * 2 + 0][0] = r0; bh[p * 2 + 0][1] = r1;
            bh[p * 2 + 1][0] = r2; bh[p * 2 + 1][1] = r3;
        }
        uint32_t ah[2][4], al[2][4];
#pragma unroll
        for (int mt = 0; mt < 2; mt++)
            LDSM_X4(ah[mt][0], ah[mt][1], ah[mt][2], ah[mt][3],
                    base + SEG_AH + aoff + (uint32_t)(mt * 2048));
#pragma unroll
        for (int mt = 0; mt < 2; mt++)
            LDSM_X4(al[mt][0], al[mt][1], al[mt][2], al[mt][3],
                    base + SEG_AL + aoff + (uint32_t)(mt * 2048));
#pragma unroll
        for (int p = 0; p < 2; p++) {
            uint32_t r0, r1, r2, r3;
            LDSM_X4(r0, r1, r2, r3, base + SEG_BL + boff + (uint32_t)(p * 2048));
            bl[p * 2 + 0][0] = r0; bl[p * 2 + 0][1] = r1;
            bl[p * 2 + 1][0] = r2; bl[p * 2 + 1][1] = r3;
        }

        // hi.hi
#pragma unroll
        for (int mt = 0; mt < 2; mt++)
#pragma unroll
            for (int nt = 0; nt < 4; nt++)
                MMA16816(acc[mt][nt], ah[mt][0], ah[mt][1], ah[mt][2], ah[mt][3],
                         bh[nt][0], bh[nt][1]);
        // lo.hi
#pragma unroll
        for (int mt = 0; mt < 2; mt++)
#pragma unroll
            for (int nt = 0; nt < 4; nt++)
                MMA16816(acc[mt][nt], al[mt][0], al[mt][1], al[mt][2], al[mt][3],
                         bh[nt][0], bh[nt][1]);
        // hi.lo
#pragma unroll
        for (int mt = 0; mt < 2; mt++)
#pragma unroll
            for (int nt = 0; nt < 4; nt++)
                MMA16816(acc[mt][nt], ah[mt][0], ah[mt][1], ah[mt][2], ah[mt][3],
                         bl[nt][0], bl[nt][1]);
    }

    // ---- epilogue straight from registers; y-info hoisted ----
    const float LOG2E = 1.44269504f;
    const int lr = l >> 2;
    const int lc = (l & 3) * 2;

    float4 ya[4], yb[4];
#pragma unroll
    for (int nt = 0; nt < 4; nt++) {
        const int c = wx * 32 + nt * 8 + lc;
        ya[nt] = *(const float4*)(smem + OFF_YI + c * 16);
        yb[nt] = *(const float4*)(smem + OFF_YI + (c + 1) * 16);
    }

#pragma unroll
    for (int mt = 0; mt < 2; mt++) {
        const int r0 = wy * 32 + mt * 16 + lr;
        const float4 xi0 = *(const float4*)(smem + OFF_XI + r0 * 16);
        const float4 xi1 = *(const float4*)(smem + OFF_XI + (r0 + 8) * 16);
        float* orow0 = out + ((size_t)b * NN + n0 + r0) * MM + m0;
        float* orow1 = orow0 + (size_t)8 * MM;
#pragma unroll
        for (int nt = 0; nt < 4; nt++) {
            const int c = wx * 32 + nt * 8 + lc;
            const float4 y0 = ya[nt];
            const float4 y1 = yb[nt];

            float z00 = xi0.z + y0.z, z01 = xi0.z + y1.z;
            float z10 = xi1.z + y0.z, z11 = xi1.z + y1.z;

            float e00, e01, e10, e11;
            asm("ex2.approx.f32 %0, %1;" : "=f"(e00)
                : "f"(fminf(fmaf(acc[mt][nt][0], LOG2E, -z00), 0.f)));
            asm("ex2.approx.f32 %0, %1;" : "=f"(e01)
                : "f"(fminf(fmaf(acc[mt][nt][1], LOG2E, -z01), 0.f)));
            asm("ex2.approx.f32 %0, %1;" : "=f"(e10)
                : "f"(fminf(fmaf(acc[mt][nt][2], LOG2E, -z10), 0.f)));
            asm("ex2.approx.f32 %0, %1;" : "=f"(e11)
                : "f"(fminf(fmaf(acc[mt][nt][3], LOG2E, -z11), 0.f)));

            float c00 = fmaf(xi0.x, y0.x, xi0.y * y0.y);
            float c01 = fmaf(xi0.x, y1.x, xi0.y * y1.y);
            float c10 = fmaf(xi1.x, y0.x, xi1.y * y0.y);
            float c11 = fmaf(xi1.x, y1.x, xi1.y * y1.y);

            *(float2*)(orow0 + c) = make_float2(c00 * e00, c01 * e01);
            *(float2*)(orow1 + c) = make_float2(c10 * e10, c11 * e11);
        }
    }
}

// ---------------------------------------------------------------------------
extern "C" void kernel_launch(void* const* d_in, const int* in_sizes, int n_in,
                              void* d_out, int out_size)
{
    const float* x     = (const float*)d_in[0];
    const float* y     = (const float*)d_in[1];
    const float* mu    = (const float*)d_in[2];
    const float* logs2 = (const float*)d_in[3];
    (void)in_sizes; (void)n_in; (void)out_size;

    cudaFuncSetAttribute(pairwise_kernel,
                         cudaFuncAttributeMaxDynamicSharedMemorySize, SMEM_TOTAL);

    dim3 pgrid((BB * NN) / 8, 2, 1);
    precomp_kernel<<<pgrid, 256>>>(x, y, mu, logs2);

    dim3 grid(MM / 64, NN / 128, BB);
    pairwise_kernel<<<grid, 256, SMEM_TOTAL>>>((float*)d_out);
}

// round 17
// speedup vs baseline: 1.1725x; 1.1725x over previous
#include <cuda_runtime.h>
#include <cuda_bf16.h>
#include <math.h>
#include <stdint.h>

// Shape fixed by dataset: x[4,4096,64], y[4,4096,64], mu[64,1], logs2diag[64]
// R17: VERBATIM resubmission of R16. R16 returned the broker-side "GB300
// container failed twice" signature; byte-identical resubmits have passed
// twice before (R7->R8, R13->R14). Design under test (vs 98.4us R14):
//   (a) front-load bh+ah+bl LDSM before first MMA (bl latency was exposed)
//   (b) st.global.cs streaming stores (keep A/B tiles resident in L2)
#define BB 4
#define NN 4096
#define MM 4096
#define DD 64

// ---------------- device scratch (no allocation allowed) -------------------
// Row layout: 16 uint4 = [hi: 8 uint4 (K=64 bf16)][lo: 8 uint4]
__device__ uint4  g_XE[BB * NN * 16];
__device__ uint4  g_YE[BB * MM * 16];
__device__ float4 g_xr[BB * NN];   // {cos(mx), sin(mx), 0.5*||x_||^2*log2e, 0}
__device__ float4 g_yr[BB * MM];

__device__ __forceinline__ uint32_t smem_u32(const void* p) {
    uint32_t a;
    asm("{ .reg .u64 t; cvta.to.shared.u64 t, %1; cvt.u32.u64 %0, t; }" : "=r"(a) : "l"(p));
    return a;
}

#define SWZ(o) ((o) ^ (((o) >> 3) & 0x70))

#define CP_ASYNC16(dst, src) \
    asm volatile("cp.async.cg.shared.global [%0], [%1], 16;" \
                 :: "r"(dst), "l"(src) : "memory")
#define CP_COMMIT() asm volatile("cp.async.commit_group;" ::: "memory")
#define CP_WAIT(n)  asm volatile("cp.async.wait_group %0;" :: "n"(n) : "memory")

#define LDSM_X4(r0, r1, r2, r3, addr)                                        \
    asm volatile("ldmatrix.sync.aligned.m8n8.x4.shared.b16 {%0,%1,%2,%3}, [%4];" \
                 : "=r"(r0), "=r"(r1), "=r"(r2), "=r"(r3) : "r"(addr))

#define MMA16816(d, a0, a1, a2, a3, b0, b1)                                  \
    asm volatile("mma.sync.aligned.m16n8k16.row.col.f32.bf16.bf16.f32 "      \
        "{%0,%1,%2,%3}, {%4,%5,%6,%7}, {%8,%9}, {%0,%1,%2,%3};"              \
        : "+f"((d)[0]), "+f"((d)[1]), "+f"((d)[2]), "+f"((d)[3])             \
        : "r"(a0), "r"(a1), "r"(a2), "r"(a3), "r"(b0), "r"(b1))

#define STG_CS_V2(ptr, v0, v1) \
    asm volatile("st.global.cs.v2.f32 [%0], {%1, %2};" \
                 :: "l"(ptr), "f"(v0), "f"(v1) : "memory")

// ---------------- SMEM layout (~68KB -> 2 CTAs/SM) --------------------------
static constexpr int SEG_AH = 0;         // Ahi: 128 rows x 128B SW128
static constexpr int SEG_AL = 16384;     // Alo
static constexpr int SEG_BH = 32768;     // Bhi
static constexpr int SEG_BL = 49152;     // Blo
static constexpr int OFF_XI = 65536;     // float4[128]
static constexpr int OFF_YI = 67584;     // float4[128]
static constexpr int SMEM_TOTAL = 69632;

// ---------------------------------------------------------------------------
// Pass 1 (single launch, gridDim.y=2): per-row precompute + bf16 split.
// ---------------------------------------------------------------------------
__global__ void precomp_kernel(const float* __restrict__ x,
                               const float* __restrict__ y,
                               const float* __restrict__ mu,
                               const float* __restrict__ logs2)
{
    int gw  = (blockIdx.x * blockDim.x + threadIdx.x) >> 5;  // row within side
    int l   = threadIdx.x & 31;
    int isY = blockIdx.y;
    const float* src = isY ? y : x;

    float2 v   = ((const float2*)src)[gw * 32 + l];
    float2 muv = ((const float2*)mu)[l];
    float2 ls  = ((const float2*)logs2)[l];

    float s0 = expf(0.5f * ls.x), s1 = expf(0.5f * ls.y);
    float a = v.x * s0, c = v.y * s1;
    float m  = fmaf(v.x, muv.x, v.y * muv.y);
    float ss = fmaf(a, a, c * c);
#pragma unroll
    for (int o = 16; o > 0; o >>= 1) {
        m  += __shfl_xor_sync(0xffffffffu, m, o);
        ss += __shfl_xor_sync(0xffffffffu, ss, o);
    }

    __nv_bfloat16 h0 = __float2bfloat16(a);
    __nv_bfloat16 h1 = __float2bfloat16(c);
    __nv_bfloat16 l0 = __float2bfloat16(a - __bfloat162float(h0));
    __nv_bfloat16 l1 = __float2bfloat16(c - __bfloat162float(h1));
    uint32_t hi = ((uint32_t)__bfloat16_as_ushort(h1) << 16) | __bfloat16_as_ushort(h0);
    uint32_t lo = ((uint32_t)__bfloat16_as_ushort(l1) << 16) | __bfloat16_as_ushort(l0);

    uint32_t* dst = (uint32_t*)(isY ? g_YE : g_XE) + (size_t)gw * 64;
    dst[l] = hi; dst[32 + l] = lo;

    if (l == 0) {
        float sn, cs;
        sincosf(m, &sn, &cs);
        float4* ri = isY ? g_yr : g_xr;
        ri[gw] = make_float4(cs, sn, 0.5f * ss * 1.44269504f, 0.f);
    }
}

// ---------------------------------------------------------------------------
// Pass 2: dedup split-bf16 mma.sync GEMM + fused epilogue.
//   CTA: 128x128 tile, 256 threads = 8 warps (2x4), warp tile 64x32, occ 2.
//   Per K16-step: bh+ah+bl front-loaded (8 independent LDSM.x4), hi.hi MMAs,
//   then per-mt al LDSM + lo.hi, then hi.lo (Ahi reused).
// ---------------------------------------------------------------------------
__global__ void __launch_bounds__(256, 2)
pairwise_kernel(float* __restrict__ out)
{
    extern __shared__ char smem[];
    const uint32_t base = smem_u32(smem);
    const int tid = threadIdx.x;
    const int wid = tid >> 5;
    const int l   = tid & 31;
    const int wy  = wid >> 2;           // 0..1 : row block (64 rows)
    const int wx  = wid & 3;            // 0..3 : col block (32 cols)

    const int b  = blockIdx.z;
    const int n0 = blockIdx.y * 128;
    const int m0 = blockIdx.x * 128;

    const uint4* Ag = g_XE + ((size_t)b * NN + n0) * 16;
    const uint4* Bg = g_YE + ((size_t)b * MM + m0) * 16;

    // ---- cp.async: 2 groups split by K-half (logical c16 0..3 then 4..7) ----
#pragma unroll
    for (int half = 0; half < 2; half++) {
#pragma unroll
        for (int i = 0; i < 2; i++) {
            int f   = i * 256 + tid;
            int row = f >> 2;
            int c16 = (f & 3) + half * 4;
            uint32_t soff = SWZ((uint32_t)(row * 128 + c16 * 16));
            CP_ASYNC16(base + SEG_AH + soff, (const void*)(Ag + row * 16 + c16));
            CP_ASYNC16(base + SEG_AL + soff, (const void*)(Ag + row * 16 + 8 + c16));
            CP_ASYNC16(base + SEG_BH + soff, (const void*)(Bg + row * 16 + c16));
            CP_ASYNC16(base + SEG_BL + soff, (const void*)(Bg + row * 16 + 8 + c16));
        }
        CP_COMMIT();
    }

    // ---- row-info staging (covered by first syncthreads) ----
    if (tid < 128)
        *(float4*)(smem + OFF_XI + tid * 16) = g_xr[(size_t)b * NN + n0 + tid];
    else
        *(float4*)(smem + OFF_YI + (tid - 128) * 16) = g_yr[(size_t)b * MM + m0 + (tid - 128)];

    // ---- per-lane ldmatrix address components ----
    const int arow  = wy * 64 + (l & 15);
    const uint32_t axor  = (uint32_t)((l & 7) * 16);
    const uint32_t ahalf = (uint32_t)((l >> 4) * 16);
    const int g     = l >> 3;
    const int brow  = wx * 32 + (g & 2) * 4 + (l & 7);
    const uint32_t bxor  = (uint32_t)((l & 7) * 16);
    const uint32_t bhalf = (uint32_t)((g & 1) * 16);

    float acc[4][4][4];
#pragma unroll
    for (int mt = 0; mt < 4; mt++)
#pragma unroll
        for (int nt = 0; nt < 4; nt++)
#pragma unroll
            for (int e = 0; e < 4; e++) acc[mt][nt][e] = 0.f;

    // ---- mainloop: 4 K16-steps ----
#pragma unroll
    for (int ks = 0; ks < 4; ks++) {
        if (ks == 0)      { CP_WAIT(1); __syncthreads(); }
        else if (ks == 2) { CP_WAIT(0); __syncthreads(); }

        const uint32_t kb   = (uint32_t)(ks * 32);
        const uint32_t aoff = (uint32_t)(arow * 128) + ((kb + ahalf) ^ axor);
        const uint32_t boff = (uint32_t)(brow * 128) + ((kb + bhalf) ^ bxor);

        // front-load: bh, ah, bl (8 independent LDSM.x4 in flight)
        uint32_t bh[4][2], bl[4][2];
#pragma unroll
        for (int p = 0; p < 2; p++) {
            uint32_t r0, r1, r2, r3;
            LDSM_X4(r0, r1, r2, r3, base + SEG_BH + boff + (uint32_t)(p * 2048));
            bh[p * 2 + 0][0] = r0; bh[p * 2 + 0][1] = r1;
            bh[p * 2 + 1][0] = r2; bh[p * 2 + 1][1] = r3;
        }
        uint32_t ah[4][4];
#pragma unroll
        for (int mt = 0; mt < 4; mt++)
            LDSM_X4(ah[mt][0], ah[mt][1], ah[mt][2], ah[mt][3],
                    base + SEG_AH + aoff + (uint32_t)(mt * 2048));
#pragma unroll
        for (int p = 0; p < 2; p++) {
            uint32_t r0, r1, r2, r3;
            LDSM_X4(r0, r1, r2, r3, base + SEG_BL + boff + (uint32_t)(p * 2048));
            bl[p * 2 + 0][0] = r0; bl[p * 2 + 0][1] = r1;
            bl[p * 2 + 1][0] = r2; bl[p * 2 + 1][1] = r3;
        }

        // hi . hi
#pragma unroll
        for (int mt = 0; mt < 4; mt++)
#pragma unroll
            for (int nt = 0; nt < 4; nt++)
                MMA16816(acc[mt][nt], ah[mt][0], ah[mt][1], ah[mt][2], ah[mt][3],
                         bh[nt][0], bh[nt][1]);

        // lo . hi  (Bhi reused; al streamed per mt)
#pragma unroll
        for (int mt = 0; mt < 4; mt++) {
            uint32_t al0, al1, al2, al3;
            LDSM_X4(al0, al1, al2, al3, base + SEG_AL + aoff + (uint32_t)(mt * 2048));
#pragma unroll
            for (int nt = 0; nt < 4; nt++)
                MMA16816(acc[mt][nt], al0, al1, al2, al3, bh[nt][0], bh[nt][1]);
        }

        // hi . lo  (Ahi + pre-loaded Blo)
#pragma unroll
        for (int mt = 0; mt < 4; mt++)
#pragma unroll
            for (int nt = 0; nt < 4; nt++)
                MMA16816(acc[mt][nt], ah[mt][0], ah[mt][1], ah[mt][2], ah[mt][3],
                         bl[nt][0], bl[nt][1]);
    }

    // ---- epilogue straight from registers; y-info hoisted ----
    const float LOG2E = 1.44269504f;
    const int lr = l >> 2;
    const int lc = (l & 3) * 2;

    float4 ya[4], yb[4];
#pragma unroll
    for (int nt = 0; nt < 4; nt++) {
        const int c = wx * 32 + nt * 8 + lc;
        ya[nt] = *(const float4*)(smem + OFF_YI + c * 16);
        yb[nt] = *(const float4*)(smem + OFF_YI + (c + 1) * 16);
    }

#pragma unroll
    for (int mt = 0; mt < 4; mt++) {
        const int r0 = wy * 64 + mt * 16 + lr;
        const float4 xi0 = *(const float4*)(smem + OFF_XI + r0 * 16);
        const float4 xi1 = *(const float4*)(smem + OFF_XI + (r0 + 8) * 16);
        float* orow0 = out + ((size_t)b * NN + n0 + r0) * MM + m0;
        float* orow1 = orow0 + (size_t)8 * MM;
#pragma unroll
        for (int nt = 0; nt < 4; nt++) {
            const int c = wx * 32 + nt * 8 + lc;
            const float4 y0 = ya[nt];
            const float4 y1 = yb[nt];

            float z00 = xi0.z + y0.z, z01 = xi0.z + y1.z;
            float z10 = xi1.z + y0.z, z11 = xi1.z + y1.z;

            float e00, e01, e10, e11;
            asm("ex2.approx.f32 %0, %1;" : "=f"(e00)
                : "f"(fminf(fmaf(acc[mt][nt][0], LOG2E, -z00), 0.f)));
            asm("ex2.approx.f32 %0, %1;" : "=f"(e01)
                : "f"(fminf(fmaf(acc[mt][nt][1], LOG2E, -z01), 0.f)));
            asm("ex2.approx.f32 %0, %1;" : "=f"(e10)
                : "f"(fminf(fmaf(acc[mt][nt][2], LOG2E, -z10), 0.f)));
            asm("ex2.approx.f32 %0, %1;" : "=f"(e11)
                : "f"(fminf(fmaf(acc[mt][nt][3], LOG2E, -z11), 0.f)));

            float c00 = fmaf(xi0.x, y0.x, xi0.y * y0.y);
            float c01 = fmaf(xi0.x, y1.x, xi0.y * y1.y);
            float c10 = fmaf(xi1.x, y0.x, xi1.y * y0.y);
            float c11 = fmaf(xi1.x, y1.x, xi1.y * y1.y);

            STG_CS_V2(orow0 + c, c00 * e00, c01 * e01);
            STG_CS_V2(orow1 + c, c10 * e10, c11 * e11);
        }
    }
}

// ---------------------------------------------------------------------------
extern "C" void kernel_launch(void* const* d_in, const int* in_sizes, int n_in,
                              void* d_out, int out_size)
{
    const float* x     = (const float*)d_in[0];
    const float* y     = (const float*)d_in[1];
    const float* mu    = (const float*)d_in[2];
    const float* logs2 = (const float*)d_in[3];
    (void)in_sizes; (void)n_in; (void)out_size;

    cudaFuncSetAttribute(pairwise_kernel,
                         cudaFuncAttributeMaxDynamicSharedMemorySize, SMEM_TOTAL);

    dim3 pgrid((BB * NN) / 8, 2, 1);
    precomp_kernel<<<pgrid, 256>>>(x, y, mu, logs2);

    dim3 grid(MM / 128, NN / 128, BB);
    pairwise_kernel<<<grid, 256, SMEM_TOTAL>>>((float*)d_out);
}